// round 9
// baseline (speedup 1.0000x reference)
#include <cuda_runtime.h>
#include <stdint.h>
#include <math.h>

#define Tsteps 16
#define NT 4096              // tiles of 64 rows (262144/64)
#define THREADS 512

// Transposed DFT fields: [c][pos], pos = u*128+v
__device__ float g_ArT[64*16384];
__device__ float g_AiT[64*16384];
__device__ float g_BrT[64*16384];
__device__ float g_BiT[64*16384];
// Stage-1 partials, layout [p][c][v]
__device__ float g_PAr[7*64*128];
__device__ float g_PAi[7*64*128];
__device__ float g_PBr[7*64*128];
__device__ float g_PBi[7*64*128];

// ---------------- helpers ----------------
static __device__ __forceinline__ unsigned long long pack2(float lo, float hi){
    unsigned long long r; asm("mov.b64 %0, {%1, %2};" : "=l"(r) : "f"(lo), "f"(hi)); return r;
}
static __device__ __forceinline__ void unpack2(unsigned long long v, float& lo, float& hi){
    asm("mov.b64 {%0, %1}, %2;" : "=f"(lo), "=f"(hi) : "l"(v));
}
static __device__ __forceinline__ unsigned long long fma2(unsigned long long a, unsigned long long b, unsigned long long c){
    unsigned long long d; asm("fma.rn.f32x2 %0, %1, %2, %3;" : "=l"(d) : "l"(a), "l"(b), "l"(c)); return d;
}
static __device__ __forceinline__ unsigned long long mul2(unsigned long long a, unsigned long long b){
    unsigned long long d; asm("mul.rn.f32x2 %0, %1, %2;" : "=l"(d) : "l"(a), "l"(b)); return d;
}
static __device__ __forceinline__ unsigned long long add2(unsigned long long a, unsigned long long b){
    unsigned long long d; asm("add.rn.f32x2 %0, %1, %2;" : "=l"(d) : "l"(a), "l"(b)); return d;
}
static __device__ __forceinline__ float sigmoidf_(float x){
    return __fdividef(1.0f, 1.0f + __expf(-x));
}
static __device__ __forceinline__ float softplusf_(float x){
    return fmaxf(x, 0.0f) + __logf(1.0f + __expf(-fabsf(x)));
}
static __device__ __forceinline__ float frcp_(float x){
    float r; asm("rcp.approx.f32 %0, %1;" : "=f"(r) : "f"(x)); return r;
}
static __device__ __forceinline__ uint32_t tf32_(float f){
    uint32_t r; asm("cvt.rna.tf32.f32 %0, %1;" : "=r"(r) : "f"(f)); return r;
}
static __device__ __forceinline__ void mma_tf32(float* d, const uint32_t* a, uint32_t b0, uint32_t b1){
    asm volatile("mma.sync.aligned.m16n8k8.row.col.f32.tf32.tf32.f32 "
        "{%0,%1,%2,%3}, {%4,%5,%6,%7}, {%8,%9}, {%0,%1,%2,%3};"
        : "+f"(d[0]), "+f"(d[1]), "+f"(d[2]), "+f"(d[3])
        : "r"(a[0]), "r"(a[1]), "r"(a[2]), "r"(a[3]), "r"(b0), "r"(b1));
}

// ---------------- DFT stage 1: row DFT over q, out [p][c][v] ----------------
// grid = 128 (v), 448 threads = 7 p-slices x 64 channels
__global__ void dft_stage1(const float* __restrict__ A_real, const float* __restrict__ A_imag,
                           const float* __restrict__ B_real, const float* __restrict__ B_imag){
    const int c = threadIdx.x & 63;
    const int p = threadIdx.x >> 6;
    const int v = blockIdx.x;
    float par = 0.f, pai = 0.f, pbr = 0.f, pbi = 0.f;
#pragma unroll
    for (int q = 0; q < 7; q++){
        int idx = (v * (q + 60)) & 127;
        float s, co; sincospif((float)idx / 64.0f, &s, &co);
        float twr = co, twi = -s;
        int ki = c*49 + p*7 + q;
        float ar = A_real[ki], ai = A_imag[ki];
        float br = B_real[ki], bi = B_imag[ki];
        par += ar*twr - ai*twi;  pai += ar*twi + ai*twr;
        pbr += br*twr - bi*twi;  pbi += br*twi + bi*twr;
    }
    int o = (p*64 + c)*128 + v;
    g_PAr[o] = par; g_PAi[o] = pai;
    g_PBr[o] = pbr; g_PBi[o] = pbi;
}

// ---------------- DFT stage 2: column DFT over p + stabilization, transposed out ----------------
__global__ void dft_stage2(){
    const int u = blockIdx.x;
    float eur[7], eui[7];
#pragma unroll
    for (int p = 0; p < 7; p++){
        int idx = (u * (p + 60)) & 127;
        float s, co; sincospif((float)idx / 64.0f, &s, &co);
        eur[p] = co; eui[p] = -s;
    }
    for (int it = 0; it < 16; it++){
        int idx = threadIdx.x + it*512;           // 0..8191
        int c = idx >> 7;
        int v = idx & 127;
        float fra = 0.f, fia = 0.f, frb = 0.f, fib = 0.f;
#pragma unroll
        for (int p = 0; p < 7; p++){
            int o = (p*64 + c)*128 + v;
            float par = g_PAr[o], pai = g_PAi[o];
            float pbr = g_PBr[o], pbi = g_PBi[o];
            fra += eur[p]*par - eui[p]*pai;  fia += eur[p]*pai + eui[p]*par;
            frb += eur[p]*pbr - eui[p]*pbi;  fib += eur[p]*pbi + eui[p]*pbr;
        }
        float mag = sqrtf(fra*fra + fia*fia + 1e-8f);
        float sc  = 0.95f * sigmoidf_(mag) / (mag + 1e-8f);
        int o = c*16384 + u*128 + v;
        g_ArT[o] = fra * sc;  g_AiT[o] = fia * sc;
        g_BrT[o] = frb;       g_BiT[o] = fib;
    }
}

// ---------------- Main: persistent mma.sync tf32 GEMM + fused SSM epilogue ----------------
// SMEM: Ws = 192KB B-fragments (persistent), As = 32KB A-fragments (tf32)
// Warp (mg = w&1, nq = w>>1): rows mg*32+..., channels 8nq+4nb+(l&3)
__global__ void __launch_bounds__(THREADS, 1)
main_kernel(const float* __restrict__ x,
            const float* __restrict__ Wf, const float* __restrict__ bfp,
            const float* __restrict__ Wi, const float* __restrict__ bip,
            const float* __restrict__ Wd, const float* __restrict__ bdp,
            float* __restrict__ out){
    extern __shared__ char smem[];
    uint2* Ws = (uint2*)smem;                          // 24576 uint2 = 192KB
    uint32_t* Asu = (uint32_t*)(smem + 196608);        // frag scatter view
    uint4*    As4 = (uint4*)(smem + 196608);           // frag read view

    const int tid = threadIdx.x;
    const int w = tid >> 5;
    const int l = tid & 31;
    const int mg = w & 1;
    const int nq = w >> 1;

    // ---- one-time: stage W fragments (tf32) ----
    for (int idx = tid; idx < 3*16*16*32; idx += THREADS){
        int lane = idx & 31;
        int ks   = (idx >> 5) & 15;
        int nbG  = (idx >> 9) & 15;
        int g    = idx >> 13;
        int n    = nbG*8 + (lane >> 2);                // j-interleaved output col
        int col  = (n >> 1) + ((n & 1) << 6);          // original output index
        int k0   = ks*8 + (lane & 3);
        const float* Wm = (g == 0) ? Wf : ((g == 1) ? Wi : Wd);
        uint2 bb;
        bb.x = tf32_(Wm[k0*128 + col]);
        bb.y = tf32_(Wm[(k0+4)*128 + col]);
        Ws[idx] = bb;
    }
    // ---- bias registers for this thread's 2 channels ----
    float bfl[2], bfh[2], bil[2], bih[2], bdl[2], bdh[2];
#pragma unroll
    for (int nb = 0; nb < 2; nb++){
        int c = 8*nq + 4*nb + (l & 3);
        bfl[nb] = bfp[c]; bfh[nb] = bfp[c+64];
        bil[nb] = bip[c]; bih[nb] = bip[c+64];
        bdl[nb] = bdp[c]; bdh[nb] = bdp[c+64];
    }
    const unsigned long long NEG1 = pack2(-1.0f, -1.0f);
    const unsigned long long ONE2 = pack2(1.0f, 1.0f);
    __syncthreads();

    for (int tile = blockIdx.x; tile < NT; tile += gridDim.x){
        const int base = tile * 64;
        const float4* xin4 = (const float4*)(x + (size_t)base * 128);

        // ---- stage A fragments (tf32, scattered into frag layout) ----
#pragma unroll
        for (int j = 0; j < 4; j++){
            int e4 = tid + j*THREADS;                  // 0..2047
            int row = e4 >> 5;
            int kq  = e4 & 31;
            float4 v = xin4[e4];
            int ks   = kq >> 1;
            int slot = ((kq & 1) << 1) | ((row >> 3) & 1);
            int lb   = (row & 7) << 2;
            int fragbase = (((row >> 4)*16 + ks) << 5);
            int sx = ks & 7;
            Asu[((fragbase + ((lb+0) ^ sx)) << 2) + slot] = tf32_(v.x);
            Asu[((fragbase + ((lb+1) ^ sx)) << 2) + slot] = tf32_(v.y);
            Asu[((fragbase + ((lb+2) ^ sx)) << 2) + slot] = tf32_(v.z);
            Asu[((fragbase + ((lb+3) ^ sx)) << 2) + slot] = tf32_(v.w);
        }
        __syncthreads();

        // ---- GEMM ----
        float acc[3][2][2][4];
#pragma unroll
        for (int g = 0; g < 3; g++)
#pragma unroll
            for (int mb = 0; mb < 2; mb++)
#pragma unroll
                for (int nb = 0; nb < 2; nb++)
#pragma unroll
                    for (int i = 0; i < 4; i++) acc[g][mb][nb][i] = 0.f;

#pragma unroll
        for (int ks = 0; ks < 16; ks++){
            uint4 Af0 = As4[((mg*2+0)*16 + ks)*32 + (l ^ (ks & 7))];
            uint4 Af1 = As4[((mg*2+1)*16 + ks)*32 + (l ^ (ks & 7))];
#pragma unroll
            for (int g = 0; g < 3; g++){
#pragma unroll
                for (int nb = 0; nb < 2; nb++){
                    uint2 bb = Ws[((g*16 + nq*2 + nb)*16 + ks)*32 + l];
                    mma_tf32(acc[g][0][nb], (const uint32_t*)&Af0, bb.x, bb.y);
                    mma_tf32(acc[g][1][nb], (const uint32_t*)&Af1, bb.x, bb.y);
                }
            }
        }
        __syncthreads();   // frags free for next tile's scatter

        // ---- epilogue: gates + closed-form recurrence; direct STG to out ----
        const int fbase = base & 16383;
#pragma unroll
        for (int mb = 0; mb < 2; mb++){
#pragma unroll
            for (int nb = 0; nb < 2; nb++){
                const int c   = 8*nq + 4*nb + (l & 3);
                const int rl0 = mg*32 + mb*16 + (l >> 2);
                const int rl1 = rl0 + 8;
                const int p0  = fbase + rl0;

                const float* af = acc[0][mb][nb];
                const float* ag = acc[1][mb][nb];
                const float* ad = acc[2][mb][nb];

                // fields (L2-resident)
                const float* ArT = g_ArT + (size_t)c*16384 + p0;
                const float* AiT = g_AiT + (size_t)c*16384 + p0;
                const float* BrT = g_BrT + (size_t)c*16384 + p0;
                const float* BiT = g_BiT + (size_t)c*16384 + p0;
                float Ar0 = ArT[0], Ar1 = ArT[8];
                float Ai0 = AiT[0], Ai1 = AiT[8];
                float Br0 = BrT[0], Br1 = BrT[8];
                float Bi0 = BiT[0], Bi1 = BiT[8];

                // exact x (L2 hit: tile just read in scatter phase)
                const float* xr0p = x + (size_t)(base + rl0)*128;
                const float* xr1p = x + (size_t)(base + rl1)*128;
                float xr0 = xr0p[c], xi0 = xr0p[64 + c];
                float xr1 = xr1p[c], xi1 = xr1p[64 + c];

                float fgr0 = sigmoidf_(af[0] + bfl[nb] + 2.0f);
                float fgi0 = sigmoidf_(af[1] + bfh[nb] + 2.0f);
                float fgr1 = sigmoidf_(af[2] + bfl[nb] + 2.0f);
                float fgi1 = sigmoidf_(af[3] + bfh[nb] + 2.0f);
                float igr0 = sigmoidf_(ag[0] + bil[nb]);
                float igi0 = sigmoidf_(ag[1] + bih[nb]);
                float igr1 = sigmoidf_(ag[2] + bil[nb]);
                float igi1 = sigmoidf_(ag[3] + bih[nb]);
                float dlr0 = softplusf_(ad[0] + bdl[nb]) * 0.1f;
                float dli0 = softplusf_(ad[1] + bdh[nb]) * 0.1f;
                float dlr1 = softplusf_(ad[2] + bdl[nb]) * 0.1f;
                float dli1 = softplusf_(ad[3] + bdh[nb]) * 0.1f;

                float Bxr0 = Br0*xr0 - Bi0*xi0, Bxi0 = Br0*xi0 + Bi0*xr0;
                float Bxr1 = Br1*xr1 - Bi1*xi1, Bxi1 = Br1*xi1 + Bi1*xr1;
                unsigned long long IR2 = pack2(dlr0*igr0*Bxr0, dlr1*igr1*Bxr1);
                unsigned long long II2 = pack2(dli0*igi0*Bxi0, dli1*igi1*Bxi1);

                // M = [[a,b],[c,d]]: a=fgr*Ar, b=-fgr*Ai, c=fgi*Ai, d=fgi*Ar
                unsigned long long a0 = pack2(fgr0*Ar0,  fgr1*Ar1);
                unsigned long long b0 = pack2(-fgr0*Ai0, -fgr1*Ai1);
                unsigned long long c0 = pack2(fgi0*Ai0,  fgi1*Ai1);
                unsigned long long d0 = pack2(fgi0*Ar0,  fgi1*Ar1);

                // P = M^16 via 4 squarings
                unsigned long long A_ = a0, B_ = b0, C_ = c0, D_ = d0;
#pragma unroll
                for (int it = 0; it < 4; it++){
                    unsigned long long s = add2(A_, D_);
                    unsigned long long p = mul2(B_, C_);
                    unsigned long long An = fma2(A_, A_, p);
                    unsigned long long Dn = fma2(D_, D_, p);
                    B_ = mul2(B_, s);
                    C_ = mul2(C_, s);
                    A_ = An; D_ = Dn;
                }
                // ip = (I - P) * inp
                unsigned long long t1 = fma2(A_, IR2, mul2(B_, II2));
                unsigned long long t2 = fma2(C_, IR2, mul2(D_, II2));
                unsigned long long ipr = fma2(t1, NEG1, IR2);
                unsigned long long ipi = fma2(t2, NEG1, II2);
                // solve (I - M) h = ip
                unsigned long long A11 = fma2(a0, NEG1, ONE2);   // 1 - a
                unsigned long long A22 = fma2(d0, NEG1, ONE2);   // 1 - d
                unsigned long long bc  = mul2(b0, c0);
                unsigned long long det = fma2(A11, A22, mul2(bc, NEG1));
                float de0, de1; unpack2(det, de0, de1);
                unsigned long long RD2 = pack2(frcp_(de0), frcp_(de1));
                unsigned long long HR = mul2(RD2, fma2(A22, ipr, mul2(b0, ipi)));
                unsigned long long HI = mul2(RD2, fma2(c0, ipr, mul2(A11, ipi)));

                float hr0, hr1, hi0, hi1;
                unpack2(HR, hr0, hr1);
                unpack2(HI, hi0, hi1);
                float* o0 = out + (size_t)(base + rl0)*128;
                float* o1 = out + (size_t)(base + rl1)*128;
                o0[c] = hr0;  o0[64 + c] = hi0;
                o1[c] = hr1;  o1[64 + c] = hi1;
            }
        }
    }
}

extern "C" void kernel_launch(void* const* d_in, const int* in_sizes, int n_in,
                              void* d_out, int out_size){
    const float* x      = (const float*)d_in[0];
    const float* Wf     = (const float*)d_in[1];
    const float* bf     = (const float*)d_in[2];
    const float* Wi     = (const float*)d_in[3];
    const float* bi     = (const float*)d_in[4];
    const float* Wd     = (const float*)d_in[5];
    const float* bd     = (const float*)d_in[6];
    const float* A_real = (const float*)d_in[7];
    const float* A_imag = (const float*)d_in[8];
    const float* B_real = (const float*)d_in[9];
    const float* B_imag = (const float*)d_in[10];
    float* out = (float*)d_out;

    dft_stage1<<<128, 448>>>(A_real, A_imag, B_real, B_imag);
    dft_stage2<<<128, 512>>>();

    const int smem_bytes = 196608 + 32768;   // 229376 <= 232448 max
    cudaFuncSetAttribute(main_kernel, cudaFuncAttributeMaxDynamicSharedMemorySize, smem_bytes);
    int dev = 0, nsm = 148;
    cudaGetDevice(&dev);
    cudaDeviceGetAttribute(&nsm, cudaDevAttrMultiProcessorCount, dev);
    main_kernel<<<nsm, THREADS, smem_bytes>>>(x, Wf, bf, Wi, bi, Wd, bd, out);
}

// round 11
// speedup vs baseline: 1.1021x; 1.1021x over previous
#include <cuda_runtime.h>
#include <stdint.h>
#include <math.h>

#define Tsteps 16
#define NT 4096              // tiles of 64 rows (262144/64)
#define THREADS 512

// Packed DFT fields: [c][pos] -> {Ar, Ai, Br, Bi}, pos = u*128+v
__device__ float4 g_F4[64*16384];
// Stage-1 partials, layout [p][c][v]
__device__ float g_PAr[7*64*128];
__device__ float g_PAi[7*64*128];
__device__ float g_PBr[7*64*128];
__device__ float g_PBi[7*64*128];

// ---------------- helpers ----------------
static __device__ __forceinline__ unsigned long long pack2(float lo, float hi){
    unsigned long long r; asm("mov.b64 %0, {%1, %2};" : "=l"(r) : "f"(lo), "f"(hi)); return r;
}
static __device__ __forceinline__ void unpack2(unsigned long long v, float& lo, float& hi){
    asm("mov.b64 {%0, %1}, %2;" : "=f"(lo), "=f"(hi) : "l"(v));
}
static __device__ __forceinline__ unsigned long long fma2(unsigned long long a, unsigned long long b, unsigned long long c){
    unsigned long long d; asm("fma.rn.f32x2 %0, %1, %2, %3;" : "=l"(d) : "l"(a), "l"(b), "l"(c)); return d;
}
static __device__ __forceinline__ unsigned long long mul2(unsigned long long a, unsigned long long b){
    unsigned long long d; asm("mul.rn.f32x2 %0, %1, %2;" : "=l"(d) : "l"(a), "l"(b)); return d;
}
static __device__ __forceinline__ unsigned long long add2(unsigned long long a, unsigned long long b){
    unsigned long long d; asm("add.rn.f32x2 %0, %1, %2;" : "=l"(d) : "l"(a), "l"(b)); return d;
}
static __device__ __forceinline__ float sigmoidf_(float x){
    return __fdividef(1.0f, 1.0f + __expf(-x));
}
static __device__ __forceinline__ float softplusf_(float x){
    return fmaxf(x, 0.0f) + __logf(1.0f + __expf(-fabsf(x)));
}
static __device__ __forceinline__ float frcp_(float x){
    float r; asm("rcp.approx.f32 %0, %1;" : "=f"(r) : "f"(x)); return r;
}
static __device__ __forceinline__ uint32_t tf32_(float f){
    uint32_t r; asm("cvt.rna.tf32.f32 %0, %1;" : "=r"(r) : "f"(f)); return r;
}
static __device__ __forceinline__ void mma_tf32(float* d, const uint32_t* a, uint32_t b0, uint32_t b1){
    asm volatile("mma.sync.aligned.m16n8k8.row.col.f32.tf32.tf32.f32 "
        "{%0,%1,%2,%3}, {%4,%5,%6,%7}, {%8,%9}, {%0,%1,%2,%3};"
        : "+f"(d[0]), "+f"(d[1]), "+f"(d[2]), "+f"(d[3])
        : "r"(a[0]), "r"(a[1]), "r"(a[2]), "r"(a[3]), "r"(b0), "r"(b1));
}

// ---------------- DFT stage 1: row DFT over q, out [p][c][v] ----------------
__global__ void dft_stage1(const float* __restrict__ A_real, const float* __restrict__ A_imag,
                           const float* __restrict__ B_real, const float* __restrict__ B_imag){
    const int c = threadIdx.x & 63;
    const int p = threadIdx.x >> 6;
    const int v = blockIdx.x;
    float par = 0.f, pai = 0.f, pbr = 0.f, pbi = 0.f;
#pragma unroll
    for (int q = 0; q < 7; q++){
        int idx = (v * (q + 60)) & 127;
        float s, co; sincospif((float)idx / 64.0f, &s, &co);
        float twr = co, twi = -s;
        int ki = c*49 + p*7 + q;
        float ar = A_real[ki], ai = A_imag[ki];
        float br = B_real[ki], bi = B_imag[ki];
        par += ar*twr - ai*twi;  pai += ar*twi + ai*twr;
        pbr += br*twr - bi*twi;  pbi += br*twi + bi*twr;
    }
    int o = (p*64 + c)*128 + v;
    g_PAr[o] = par; g_PAi[o] = pai;
    g_PBr[o] = pbr; g_PBi[o] = pbi;
}

// ---------------- DFT stage 2: column DFT over p + stabilization, packed float4 out ----------------
__global__ void dft_stage2(){
    const int u = blockIdx.x;
    float eur[7], eui[7];
#pragma unroll
    for (int p = 0; p < 7; p++){
        int idx = (u * (p + 60)) & 127;
        float s, co; sincospif((float)idx / 64.0f, &s, &co);
        eur[p] = co; eui[p] = -s;
    }
    for (int it = 0; it < 16; it++){
        int idx = threadIdx.x + it*512;           // 0..8191
        int c = idx >> 7;
        int v = idx & 127;
        float fra = 0.f, fia = 0.f, frb = 0.f, fib = 0.f;
#pragma unroll
        for (int p = 0; p < 7; p++){
            int o = (p*64 + c)*128 + v;
            float par = g_PAr[o], pai = g_PAi[o];
            float pbr = g_PBr[o], pbi = g_PBi[o];
            fra += eur[p]*par - eui[p]*pai;  fia += eur[p]*pai + eui[p]*par;
            frb += eur[p]*pbr - eui[p]*pbi;  fib += eur[p]*pbi + eui[p]*pbr;
        }
        float mag = sqrtf(fra*fra + fia*fia + 1e-8f);
        float sc  = 0.95f * sigmoidf_(mag) / (mag + 1e-8f);
        float4 f; f.x = fra * sc; f.y = fia * sc; f.z = frb; f.w = fib;
        g_F4[c*16384 + u*128 + v] = f;
    }
}

// ---------------- Main: persistent mma.sync tf32 GEMM + fused SSM epilogue ----------------
// SMEM: Ws = 192KB B-fragments (persistent), As = 32KB A-fragments (tf32)
__global__ void __launch_bounds__(THREADS, 1)
main_kernel(const float* __restrict__ x,
            const float* __restrict__ Wf, const float* __restrict__ bfp,
            const float* __restrict__ Wi, const float* __restrict__ bip,
            const float* __restrict__ Wd, const float* __restrict__ bdp,
            float* __restrict__ out){
    extern __shared__ char smem[];
    uint2* Ws = (uint2*)smem;                          // 24576 uint2 = 192KB
    uint32_t* Asu = (uint32_t*)(smem + 196608);        // frag scatter view
    uint4*    As4 = (uint4*)(smem + 196608);           // frag read view

    const int tid = threadIdx.x;
    const int w = tid >> 5;
    const int l = tid & 31;
    const int mg = w & 1;
    const int nq = w >> 1;

    // ---- one-time: stage W fragments (tf32) ----
    for (int idx = tid; idx < 3*16*16*32; idx += THREADS){
        int lane = idx & 31;
        int ks   = (idx >> 5) & 15;
        int nbG  = (idx >> 9) & 15;
        int g    = idx >> 13;
        int n    = nbG*8 + (lane >> 2);                // j-interleaved output col
        int col  = (n >> 1) + ((n & 1) << 6);          // original output index
        int k0   = ks*8 + (lane & 3);
        const float* Wm = (g == 0) ? Wf : ((g == 1) ? Wi : Wd);
        uint2 bb;
        bb.x = tf32_(Wm[k0*128 + col]);
        bb.y = tf32_(Wm[(k0+4)*128 + col]);
        Ws[idx] = bb;
    }
    // ---- bias registers for this thread's 2 channels ----
    float bfl[2], bfh[2], bil[2], bih[2], bdl[2], bdh[2];
#pragma unroll
    for (int nb = 0; nb < 2; nb++){
        int c = 8*nq + 4*nb + (l & 3);
        bfl[nb] = bfp[c]; bfh[nb] = bfp[c+64];
        bil[nb] = bip[c]; bih[nb] = bip[c+64];
        bdl[nb] = bdp[c]; bdh[nb] = bdp[c+64];
    }
    const unsigned long long NEG1 = pack2(-1.0f, -1.0f);
    const unsigned long long ONE2 = pack2(1.0f, 1.0f);

    // ---- prologue: prefetch first tile's x ----
    float4 xv[4];
    {
        int t0 = (blockIdx.x < NT) ? blockIdx.x : 0;
        const float4* xin4 = (const float4*)(x + (size_t)t0 * 64 * 128);
#pragma unroll
        for (int j = 0; j < 4; j++) xv[j] = xin4[tid + j*THREADS];
    }
    __syncthreads();

    for (int tile = blockIdx.x; tile < NT; tile += gridDim.x){
        const int base = tile * 64;

        // ---- scatter prefetched A fragments (tf32) into frag layout ----
#pragma unroll
        for (int j = 0; j < 4; j++){
            int e4 = tid + j*THREADS;                  // 0..2047
            int row = e4 >> 5;
            int kq  = e4 & 31;
            float4 v = xv[j];
            int ks   = kq >> 1;
            int slot = ((kq & 1) << 1) | ((row >> 3) & 1);
            int lb   = (row & 7) << 2;
            int fragbase = (((row >> 4)*16 + ks) << 5);
            int sx = ks & 7;
            Asu[((fragbase + ((lb+0) ^ sx)) << 2) + slot] = tf32_(v.x);
            Asu[((fragbase + ((lb+1) ^ sx)) << 2) + slot] = tf32_(v.y);
            Asu[((fragbase + ((lb+2) ^ sx)) << 2) + slot] = tf32_(v.z);
            Asu[((fragbase + ((lb+3) ^ sx)) << 2) + slot] = tf32_(v.w);
        }
        __syncthreads();

        // ---- GEMM ----
        float acc[3][2][2][4];
#pragma unroll
        for (int g = 0; g < 3; g++)
#pragma unroll
            for (int mb = 0; mb < 2; mb++)
#pragma unroll
                for (int nb = 0; nb < 2; nb++)
#pragma unroll
                    for (int i = 0; i < 4; i++) acc[g][mb][nb][i] = 0.f;

#pragma unroll
        for (int ks = 0; ks < 16; ks++){
            uint4 Af0 = As4[((mg*2+0)*16 + ks)*32 + (l ^ (ks & 7))];
            uint4 Af1 = As4[((mg*2+1)*16 + ks)*32 + (l ^ (ks & 7))];
#pragma unroll
            for (int g = 0; g < 3; g++){
#pragma unroll
                for (int nb = 0; nb < 2; nb++){
                    uint2 bb = Ws[((g*16 + nq*2 + nb)*16 + ks)*32 + l];
                    mma_tf32(acc[g][0][nb], (const uint32_t*)&Af0, bb.x, bb.y);
                    mma_tf32(acc[g][1][nb], (const uint32_t*)&Af1, bb.x, bb.y);
                }
            }
        }
        __syncthreads();   // frags free for next tile's scatter

        // ---- prefetch NEXT tile's x (hides DRAM latency under epilogue) ----
        {
            int nt2 = tile + gridDim.x;
            if (nt2 >= NT) nt2 = tile;   // harmless dummy re-read on last iter
            const float4* nx4 = (const float4*)(x + (size_t)nt2 * 64 * 128);
#pragma unroll
            for (int j = 0; j < 4; j++) xv[j] = nx4[tid + j*THREADS];
        }

        // ---- epilogue: gates + closed-form recurrence; direct STG to out ----
        const int fbase = base & 16383;
#pragma unroll
        for (int mb = 0; mb < 2; mb++){
            const int rl0 = mg*32 + mb*16 + (l >> 2);
            const int rl1 = rl0 + 8;
            const int p0  = fbase + rl0;
            const float* xr0p = x + (size_t)(base + rl0)*128;
            const float* xr1p = x + (size_t)(base + rl1)*128;

            // grouped loads for both nb (high MLP before math)
            float4 Fd[2][2];
            float xr_[2][2], xi_[2][2];
#pragma unroll
            for (int nb = 0; nb < 2; nb++){
                const int c = 8*nq + 4*nb + (l & 3);
                const float4* fp = g_F4 + (size_t)c*16384 + p0;
                Fd[nb][0] = fp[0];
                Fd[nb][1] = fp[8];
                xr_[nb][0] = xr0p[c];  xi_[nb][0] = xr0p[64 + c];
                xr_[nb][1] = xr1p[c];  xi_[nb][1] = xr1p[64 + c];
            }

#pragma unroll
            for (int nb = 0; nb < 2; nb++){
                const int c = 8*nq + 4*nb + (l & 3);
                const float* af = acc[0][mb][nb];
                const float* ag = acc[1][mb][nb];
                const float* ad = acc[2][mb][nb];

                float Ar0 = Fd[nb][0].x, Ai0 = Fd[nb][0].y, Br0 = Fd[nb][0].z, Bi0 = Fd[nb][0].w;
                float Ar1 = Fd[nb][1].x, Ai1 = Fd[nb][1].y, Br1 = Fd[nb][1].z, Bi1 = Fd[nb][1].w;

                float fgr0 = sigmoidf_(af[0] + bfl[nb] + 2.0f);
                float fgi0 = sigmoidf_(af[1] + bfh[nb] + 2.0f);
                float fgr1 = sigmoidf_(af[2] + bfl[nb] + 2.0f);
                float fgi1 = sigmoidf_(af[3] + bfh[nb] + 2.0f);
                float igr0 = sigmoidf_(ag[0] + bil[nb]);
                float igi0 = sigmoidf_(ag[1] + bih[nb]);
                float igr1 = sigmoidf_(ag[2] + bil[nb]);
                float igi1 = sigmoidf_(ag[3] + bih[nb]);
                float dlr0 = softplusf_(ad[0] + bdl[nb]) * 0.1f;
                float dli0 = softplusf_(ad[1] + bdh[nb]) * 0.1f;
                float dlr1 = softplusf_(ad[2] + bdl[nb]) * 0.1f;
                float dli1 = softplusf_(ad[3] + bdh[nb]) * 0.1f;

                float Bxr0 = Br0*xr_[nb][0] - Bi0*xi_[nb][0];
                float Bxi0 = Br0*xi_[nb][0] + Bi0*xr_[nb][0];
                float Bxr1 = Br1*xr_[nb][1] - Bi1*xi_[nb][1];
                float Bxi1 = Br1*xi_[nb][1] + Bi1*xr_[nb][1];
                unsigned long long IR2 = pack2(dlr0*igr0*Bxr0, dlr1*igr1*Bxr1);
                unsigned long long II2 = pack2(dli0*igi0*Bxi0, dli1*igi1*Bxi1);

                // M = [[a,b],[c,d]]: a=fgr*Ar, b=-fgr*Ai, c=fgi*Ai, d=fgi*Ar
                unsigned long long a0 = pack2(fgr0*Ar0,  fgr1*Ar1);
                unsigned long long b0 = pack2(-fgr0*Ai0, -fgr1*Ai1);
                unsigned long long c0 = pack2(fgi0*Ai0,  fgi1*Ai1);
                unsigned long long d0 = pack2(fgi0*Ar0,  fgi1*Ar1);

                // P = M^16 via 4 squarings
                unsigned long long A_ = a0, B_ = b0, C_ = c0, D_ = d0;
#pragma unroll
                for (int it = 0; it < 4; it++){
                    unsigned long long s = add2(A_, D_);
                    unsigned long long p = mul2(B_, C_);
                    unsigned long long An = fma2(A_, A_, p);
                    unsigned long long Dn = fma2(D_, D_, p);
                    B_ = mul2(B_, s);
                    C_ = mul2(C_, s);
                    A_ = An; D_ = Dn;
                }
                // ip = (I - P) * inp
                unsigned long long t1 = fma2(A_, IR2, mul2(B_, II2));
                unsigned long long t2 = fma2(C_, IR2, mul2(D_, II2));
                unsigned long long ipr = fma2(t1, NEG1, IR2);
                unsigned long long ipi = fma2(t2, NEG1, II2);
                // solve (I - M) h = ip
                unsigned long long A11 = fma2(a0, NEG1, ONE2);
                unsigned long long A22 = fma2(d0, NEG1, ONE2);
                unsigned long long bc  = mul2(b0, c0);
                unsigned long long det = fma2(A11, A22, mul2(bc, NEG1));
                float de0, de1; unpack2(det, de0, de1);
                unsigned long long RD2 = pack2(frcp_(de0), frcp_(de1));
                unsigned long long HR = mul2(RD2, fma2(A22, ipr, mul2(b0, ipi)));
                unsigned long long HI = mul2(RD2, fma2(c0, ipr, mul2(A11, ipi)));

                float hr0, hr1, hi0, hi1;
                unpack2(HR, hr0, hr1);
                unpack2(HI, hi0, hi1);
                float* o0 = out + (size_t)(base + rl0)*128;
                float* o1 = out + (size_t)(base + rl1)*128;
                o0[c] = hr0;  o0[64 + c] = hi0;
                o1[c] = hr1;  o1[64 + c] = hi1;
            }
        }
    }
}

extern "C" void kernel_launch(void* const* d_in, const int* in_sizes, int n_in,
                              void* d_out, int out_size){
    const float* x      = (const float*)d_in[0];
    const float* Wf     = (const float*)d_in[1];
    const float* bf     = (const float*)d_in[2];
    const float* Wi     = (const float*)d_in[3];
    const float* bi     = (const float*)d_in[4];
    const float* Wd     = (const float*)d_in[5];
    const float* bd     = (const float*)d_in[6];
    const float* A_real = (const float*)d_in[7];
    const float* A_imag = (const float*)d_in[8];
    const float* B_real = (const float*)d_in[9];
    const float* B_imag = (const float*)d_in[10];
    float* out = (float*)d_out;

    dft_stage1<<<128, 448>>>(A_real, A_imag, B_real, B_imag);
    dft_stage2<<<128, 512>>>();

    const int smem_bytes = 196608 + 32768;   // 229376 <= 232448 max
    cudaFuncSetAttribute(main_kernel, cudaFuncAttributeMaxDynamicSharedMemorySize, smem_bytes);
    int dev = 0, nsm = 148;
    cudaGetDevice(&dev);
    cudaDeviceGetAttribute(&nsm, cudaDevAttrMultiProcessorCount, dev);
    main_kernel<<<nsm, THREADS, smem_bytes>>>(x, Wf, bf, Wi, bi, Wd, bd, out);
}